// round 2
// baseline (speedup 1.0000x reference)
#include <cuda_runtime.h>
#include <cstdint>

#define NNODES 40000
#define INDIM  128
#define HID    64
#define NEDGES 640000

// ---------------- scratch (device globals: no allocs allowed) ----------------
__device__ float g_y[NNODES * HID];    // lin_l(x) per node (message space)
__device__ float g_r[NNODES * HID];    // lin_r(x) per node (root term)
__device__ float g_agg[NNODES * HID];  // scatter-add accumulator
__device__ float g_h[NNODES * HID];    // layer-1 activation
__device__ float g_cnt[NNODES];        // degree -> 1/max(deg,1)

// ---------------- init: zero agg + cnt ----------------
__global__ void k_zero() {
    int idx = blockIdx.x * blockDim.x + threadIdx.x;
    if (idx < NNODES * HID / 4)
        ((float4*)g_agg)[idx] = make_float4(0.f, 0.f, 0.f, 0.f);
    if (idx < NNODES / 4)
        ((float4*)g_cnt)[idx] = make_float4(0.f, 0.f, 0.f, 0.f);
}

// ---------------- degree count ----------------
__global__ void k_count(const int* __restrict__ ei) {
    int e = blockIdx.x * blockDim.x + threadIdx.x;
    if (e < NEDGES) atomicAdd(&g_cnt[ei[NEDGES + e]], 1.0f);
}

__global__ void k_inv() {
    int i = blockIdx.x * blockDim.x + threadIdx.x;
    if (i < NNODES) g_cnt[i] = 1.0f / fmaxf(g_cnt[i], 1.0f);
}

// ---------------- dual GEMM: [Y|R] = X @ [Wl|Wr]^T ----------------
// C[row][k] = sum_d X[row][d] * W[k][d], k in [0,128): k<64 -> Wl -> g_y,
// else Wr -> g_r. Block: 128 rows x 128 k. 256 threads; each thread:
// 4 k-columns x 16 rows (8 row-pairs packed as f32x2) -> fma.rn.f32x2.
template <int KI, bool FROMH>
__global__ __launch_bounds__(256, 2) void k_gemm_dual(
    const float* __restrict__ Xin, const float* __restrict__ Wl,
    const float* __restrict__ Wr) {
    __shared__ float Ws[32][132];  // [d][k]   (132: 16B-aligned rows, conflict-free reads)
    __shared__ float Xs[32][136];  // [d][row] (136: even stride -> aligned LDS.64)

    const float* __restrict__ X = FROMH ? (const float*)g_h : Xin;

    const int t  = threadIdx.x;
    const int tc = t & 31;          // k-group 0..31
    const int tw = t >> 5;          // warp 0..7
    const int k0 = tc << 2;         // 4 consecutive k
    const int r0 = tw << 4;         // 16 rows per warp
    const int rowBase = blockIdx.x << 7;

    unsigned long long acc[4][8];
#pragma unroll
    for (int a = 0; a < 4; a++)
#pragma unroll
        for (int b = 0; b < 8; b++) acc[a][b] = 0ULL;

    const int kw   = t >> 1;        // weight row 0..127
    const int part = t & 1;
    const float* __restrict__ Wg =
        (kw < HID) ? (Wl + (size_t)kw * KI) : (Wr + (size_t)(kw - HID) * KI);
    const int lrow = t >> 1;        // local X row 0..127
    const int grow = rowBase + lrow;

#pragma unroll 1
    for (int d0 = 0; d0 < KI; d0 += 32) {
        // stage W chunk transposed: Ws[d][k]
#pragma unroll
        for (int j = 0; j < 4; j++) {
            float4 w = *(const float4*)(Wg + d0 + part * 16 + j * 4);
            int dd = part * 16 + j * 4;
            Ws[dd + 0][kw] = w.x; Ws[dd + 1][kw] = w.y;
            Ws[dd + 2][kw] = w.z; Ws[dd + 3][kw] = w.w;
        }
        // stage X chunk transposed: Xs[d][row]
#pragma unroll
        for (int j = 0; j < 4; j++) {
            float4 v = make_float4(0.f, 0.f, 0.f, 0.f);
            if (grow < NNODES)
                v = *(const float4*)(X + (size_t)grow * KI + d0 + part * 16 + j * 4);
            int dd = part * 16 + j * 4;
            Xs[dd + 0][lrow] = v.x; Xs[dd + 1][lrow] = v.y;
            Xs[dd + 2][lrow] = v.z; Xs[dd + 3][lrow] = v.w;
        }
        __syncthreads();

#pragma unroll
        for (int d = 0; d < 32; d++) {
            float4 wv = *(const float4*)&Ws[d][k0];
            unsigned long long w2[4];
            unsigned int wu;
            wu = __float_as_uint(wv.x); asm("mov.b64 %0, {%1,%1};" : "=l"(w2[0]) : "r"(wu));
            wu = __float_as_uint(wv.y); asm("mov.b64 %0, {%1,%1};" : "=l"(w2[1]) : "r"(wu));
            wu = __float_as_uint(wv.z); asm("mov.b64 %0, {%1,%1};" : "=l"(w2[2]) : "r"(wu));
            wu = __float_as_uint(wv.w); asm("mov.b64 %0, {%1,%1};" : "=l"(w2[3]) : "r"(wu));
#pragma unroll
            for (int j = 0; j < 8; j++) {
                unsigned long long xp =
                    *(const unsigned long long*)&Xs[d][r0 + 2 * j];
#pragma unroll
                for (int kk = 0; kk < 4; kk++)
                    asm("fma.rn.f32x2 %0, %1, %2, %0;"
                        : "+l"(acc[kk][j]) : "l"(w2[kk]), "l"(xp));
            }
        }
        __syncthreads();
    }

    // epilogue: scatter 4k x 16 rows to g_y / g_r
    float* __restrict__ Obase = (k0 < HID) ? (g_y + k0) : (g_r + (k0 - HID));
#pragma unroll
    for (int j = 0; j < 8; j++) {
        int row = rowBase + r0 + 2 * j;
        float2 f[4];
#pragma unroll
        for (int kk = 0; kk < 4; kk++) f[kk] = *(float2*)&acc[kk][j];
        if (row < NNODES) {
            float4 lo = make_float4(f[0].x, f[1].x, f[2].x, f[3].x);
            *(float4*)(Obase + (size_t)row * HID) = lo;
        }
        if (row + 1 < NNODES) {
            float4 hi = make_float4(f[0].y, f[1].y, f[2].y, f[3].y);
            *(float4*)(Obase + (size_t)(row + 1) * HID) = hi;
        }
    }
}

// ---------------- edge aggregation: agg[dst] += y[src] ----------------
// 16 threads per edge, one float4 gather + one vector reduction each.
__global__ void k_aggregate(const int* __restrict__ ei) {
    int gid = blockIdx.x * blockDim.x + threadIdx.x;
    int e = gid >> 4;
    if (e >= NEDGES) return;
    int c   = (gid & 15) << 2;
    int src = __ldg(&ei[e]);
    int dst = __ldg(&ei[NEDGES + e]);
    float4 v = *(const float4*)(g_y + (size_t)src * HID + c);
    float* p = g_agg + (size_t)dst * HID + c;
    asm volatile("red.global.add.v4.f32 [%0], {%1,%2,%3,%4};"
                 :: "l"(p), "f"(v.x), "f"(v.y), "f"(v.z), "f"(v.w)
                 : "memory");
}

// ---------------- epilogue 1: h = relu(agg*inv + b1 + r); agg = 0 ----------
__global__ void k_epi1(const float* __restrict__ b1) {
    int idx = blockIdx.x * blockDim.x + threadIdx.x;
    if (idx >= NNODES * 16) return;
    int i = idx >> 4;
    float inv = g_cnt[i];
    float4 a = ((float4*)g_agg)[idx];
    float4 r = ((const float4*)g_r)[idx];
    float4 b = ((const float4*)b1)[idx & 15];
    float4 h;
    h.x = fmaxf(fmaf(a.x, inv, b.x + r.x), 0.f);
    h.y = fmaxf(fmaf(a.y, inv, b.y + r.y), 0.f);
    h.z = fmaxf(fmaf(a.z, inv, b.z + r.z), 0.f);
    h.w = fmaxf(fmaf(a.w, inv, b.w + r.w), 0.f);
    ((float4*)g_h)[idx] = h;
    ((float4*)g_agg)[idx] = make_float4(0.f, 0.f, 0.f, 0.f);
}

// ---------------- epilogue 2: z = agg*inv + b2 + r -> d_out ----------------
__global__ void k_epi2(const float* __restrict__ b2, float* __restrict__ out) {
    int idx = blockIdx.x * blockDim.x + threadIdx.x;
    if (idx >= NNODES * 16) return;
    int i = idx >> 4;
    float inv = g_cnt[i];
    float4 a = ((float4*)g_agg)[idx];
    float4 r = ((const float4*)g_r)[idx];
    float4 b = ((const float4*)b2)[idx & 15];
    float4 z;
    z.x = fmaf(a.x, inv, b.x + r.x);
    z.y = fmaf(a.y, inv, b.y + r.y);
    z.z = fmaf(a.z, inv, b.z + r.z);
    z.w = fmaf(a.w, inv, b.w + r.w);
    ((float4*)out)[idx] = z;
}

// ---------------- launch ----------------
extern "C" void kernel_launch(void* const* d_in, const int* in_sizes, int n_in,
                              void* d_out, int out_size) {
    const float* x   = (const float*)d_in[0];
    const int*   ei  = (const int*)d_in[1];
    const float* W1l = (const float*)d_in[2];
    const float* b1  = (const float*)d_in[3];
    const float* W1r = (const float*)d_in[4];
    const float* W2l = (const float*)d_in[5];
    const float* b2  = (const float*)d_in[6];
    const float* W2r = (const float*)d_in[7];
    float* out = (float*)d_out;

    const int nEpi   = NNODES * 16;                  // float4 elements of N*64
    const int gEpi   = (nEpi + 255) / 256;
    const int gGemm  = (NNODES + 127) / 128;         // 313
    const int gAgg   = (NEDGES * 16) / 256;          // 40000

    k_zero<<<gEpi, 256>>>();
    k_count<<<(NEDGES + 255) / 256, 256>>>(ei);
    k_inv<<<(NNODES + 255) / 256, 256>>>();

    // layer 1
    k_gemm_dual<INDIM, false><<<gGemm, 256>>>(x, W1l, W1r);
    k_aggregate<<<gAgg, 256>>>(ei);
    k_epi1<<<gEpi, 256>>>(b1);

    // layer 2
    k_gemm_dual<HID, true><<<gGemm, 256>>>(nullptr, W2l, W2r);
    k_aggregate<<<gAgg, 256>>>(ei);
    k_epi2<<<gEpi, 256>>>(b2, out);
}

// round 6
// speedup vs baseline: 1.2380x; 1.2380x over previous
#include <cuda_runtime.h>
#include <cstdint>

#define NNODES 40000
#define INDIM  128
#define HID    64
#define NEDGES 640000
#define NB_SCAN 157           // ceil(40000/256)

typedef unsigned long long ull;

// ---------------- scratch (device globals) ----------------
__device__ float g_y[NNODES * HID];    // lin_l(x) per node
__device__ float g_r[NNODES * HID];    // lin_r(x) per node
__device__ float g_h[NNODES * HID];    // layer-1 activation
__device__ float g_inv[NNODES];        // 1/max(deg,1)
__device__ int   g_deg[NNODES];
__device__ int   g_off[NNODES + 1];
__device__ int   g_cursor[NNODES];
__device__ int   g_csr[NEDGES];        // src ids grouped by dst
__device__ int   g_bsum[NB_SCAN];
__device__ int   g_bbase[NB_SCAN];

// ---------------- zero degrees ----------------
__global__ void k_zero_deg() {
    int i = blockIdx.x * blockDim.x + threadIdx.x;
    if (i < NNODES) g_deg[i] = 0;
}

// ---------------- degree count ----------------
__global__ void k_count(const int* __restrict__ ei) {
    int e = blockIdx.x * blockDim.x + threadIdx.x;
    if (e < NEDGES) atomicAdd(&g_deg[ei[NEDGES + e]], 1);
}

// ---------------- block scan helpers ----------------
__device__ __forceinline__ int warp_incl_scan(int v, int lane) {
#pragma unroll
    for (int o = 1; o < 32; o <<= 1) {
        int n = __shfl_up_sync(0xffffffffu, v, o);
        if (lane >= o) v += n;
    }
    return v;
}

// exclusive scan over 256 values; *total gets block sum
__device__ __forceinline__ int block_excl_scan256(int v, int tid, int* total) {
    __shared__ int warpsum[8];
    int lane = tid & 31, wid = tid >> 5;
    int incl = warp_incl_scan(v, lane);
    if (lane == 31) warpsum[wid] = incl;
    __syncthreads();
    if (wid == 0) {
        int ws = (lane < 8) ? warpsum[lane] : 0;
        ws = warp_incl_scan(ws, lane);
        if (lane < 8) warpsum[lane] = ws;
    }
    __syncthreads();
    int base = wid ? warpsum[wid - 1] : 0;
    if (total) *total = warpsum[7];
    return base + incl - v;
}

// ---------------- scan phase A: per-block degree sums ----------------
__global__ void k_scanA() {
    int i = blockIdx.x * 256 + threadIdx.x;
    int v = (i < NNODES) ? g_deg[i] : 0;
    int tot;
    block_excl_scan256(v, threadIdx.x, &tot);
    if (threadIdx.x == 0) g_bsum[blockIdx.x] = tot;
}

// ---------------- scan phase B: scan block sums (1 block) ----------------
__global__ void k_scanB() {
    int i = threadIdx.x;
    int v = (i < NB_SCAN) ? g_bsum[i] : 0;
    int ex = block_excl_scan256(v, i, nullptr);
    if (i < NB_SCAN) g_bbase[i] = ex;
}

// ---------------- scan phase C: final offsets + cursor + inv ------------
__global__ void k_scanC() {
    int i = blockIdx.x * 256 + threadIdx.x;
    int d = (i < NNODES) ? g_deg[i] : 0;
    int ex = block_excl_scan256(d, threadIdx.x, nullptr);
    if (i < NNODES) {
        int off = g_bbase[blockIdx.x] + ex;
        g_off[i] = off;
        g_cursor[i] = off;
        g_inv[i] = 1.0f / fmaxf((float)d, 1.0f);
    }
    if (i == 0) g_off[NNODES] = NEDGES;
}

// ---------------- scatter edges into CSR ----------------
__global__ void k_scatter(const int* __restrict__ ei) {
    int e = blockIdx.x * blockDim.x + threadIdx.x;
    if (e >= NEDGES) return;
    int src = __ldg(&ei[e]);
    int dst = __ldg(&ei[NEDGES + e]);
    int pos = atomicAdd(&g_cursor[dst], 1);
    g_csr[pos] = src;
}

// ---------------- dual GEMM: [Y|R] = X @ [Wl|Wr]^T ----------------
// Block: 64 rows x 128 k, 256 threads. Thread: 4 k x 8 rows (4 f32x2 pairs).
// 40000 % 64 == 0 -> no row bounds checks.
template <int KI, bool FROMH>
__global__ __launch_bounds__(256, 4) void k_gemm_dual(
    const float* __restrict__ Xin, const float* __restrict__ Wl,
    const float* __restrict__ Wr) {
    __shared__ float Ws[32][132];  // [d][k]
    __shared__ float Xs[32][66];   // [d][row]

    const float* __restrict__ X = FROMH ? (const float*)g_h : Xin;

    const int t  = threadIdx.x;
    const int tc = t & 31;            // k-group
    const int tw = t >> 5;            // warp
    const int k0 = tc << 2;
    const int r0 = tw << 3;           // 8 rows per warp
    const int rowBase = blockIdx.x << 6;

    ull acc[4][4];
#pragma unroll
    for (int a = 0; a < 4; a++)
#pragma unroll
        for (int b = 0; b < 4; b++) acc[a][b] = 0ULL;

    const int kw    = t >> 1;         // weight row 0..127
    const int partW = t & 1;
    const float* __restrict__ Wg =
        (kw < HID) ? (Wl + (size_t)kw * KI) : (Wr + (size_t)(kw - HID) * KI);
    const int lrow  = t >> 2;         // X row 0..63
    const int partX = t & 3;
    const float* __restrict__ Xg =
        X + (size_t)(rowBase + lrow) * KI + partX * 8;

#pragma unroll 1
    for (int d0 = 0; d0 < KI; d0 += 32) {
#pragma unroll
        for (int j = 0; j < 4; j++) {
            float4 w = *(const float4*)(Wg + d0 + partW * 16 + j * 4);
            int dd = partW * 16 + j * 4;
            Ws[dd + 0][kw] = w.x; Ws[dd + 1][kw] = w.y;
            Ws[dd + 2][kw] = w.z; Ws[dd + 3][kw] = w.w;
        }
#pragma unroll
        for (int j = 0; j < 2; j++) {
            float4 v = *(const float4*)(Xg + d0 + j * 4);
            int dd = partX * 8 + j * 4;
            Xs[dd + 0][lrow] = v.x; Xs[dd + 1][lrow] = v.y;
            Xs[dd + 2][lrow] = v.z; Xs[dd + 3][lrow] = v.w;
        }
        __syncthreads();

#pragma unroll
        for (int d = 0; d < 32; d++) {
            float4 wv = *(const float4*)&Ws[d][k0];
            ull w2[4];
            unsigned int wu;
            wu = __float_as_uint(wv.x); asm("mov.b64 %0, {%1,%1};" : "=l"(w2[0]) : "r"(wu));
            wu = __float_as_uint(wv.y); asm("mov.b64 %0, {%1,%1};" : "=l"(w2[1]) : "r"(wu));
            wu = __float_as_uint(wv.z); asm("mov.b64 %0, {%1,%1};" : "=l"(w2[2]) : "r"(wu));
            wu = __float_as_uint(wv.w); asm("mov.b64 %0, {%1,%1};" : "=l"(w2[3]) : "r"(wu));
#pragma unroll
            for (int j = 0; j < 4; j++) {
                ull xp = *(const ull*)&Xs[d][r0 + 2 * j];
#pragma unroll
                for (int kk = 0; kk < 4; kk++)
                    asm("fma.rn.f32x2 %0, %1, %2, %0;"
                        : "+l"(acc[kk][j]) : "l"(w2[kk]), "l"(xp));
            }
        }
        __syncthreads();
    }

    float* __restrict__ Obase = (k0 < HID) ? (g_y + k0) : (g_r + (k0 - HID));
#pragma unroll
    for (int j = 0; j < 4; j++) {
        int row = rowBase + r0 + 2 * j;
        float2 f[4];
#pragma unroll
        for (int kk = 0; kk < 4; kk++) f[kk] = *(float2*)&acc[kk][j];
        float4 lo = make_float4(f[0].x, f[1].x, f[2].x, f[3].x);
        float4 hi = make_float4(f[0].y, f[1].y, f[2].y, f[3].y);
        *(float4*)(Obase + (size_t)row * HID) = lo;
        *(float4*)(Obase + (size_t)(row + 1) * HID) = hi;
    }
}

// ---------------- pull aggregation fused with epilogue ----------------
// One warp per dst node: out = mean(y[neighbors]) + bias + r  [+ relu]
// TOH: write to g_h (device global, resolved in DEVICE code); else to outp.
template <bool RELU, bool TOH>
__global__ __launch_bounds__(256) void k_pull(
    const float* __restrict__ bias, float* __restrict__ outp) {
    int w = (blockIdx.x * blockDim.x + threadIdx.x) >> 5;
    int lane = threadIdx.x & 31;
    if (w >= NNODES) return;

    int beg = g_off[w], end = g_off[w + 1];
    float2 acc = make_float2(0.f, 0.f);

    for (int base = beg; base < end; base += 32) {
        int idx = base + lane;
        int my = (idx < end) ? g_csr[idx] : 0;
        int m = min(32, end - base);
#pragma unroll 4
        for (int j = 0; j < m; j++) {
            int s = __shfl_sync(0xffffffffu, my, j);
            float2 v = *(const float2*)(g_y + (size_t)s * HID + lane * 2);
            acc.x += v.x; acc.y += v.y;
        }
    }

    float inv = g_inv[w];
    float2 r = *(const float2*)(g_r + (size_t)w * HID + lane * 2);
    float2 b = *(const float2*)(bias + lane * 2);
    float2 o;
    o.x = fmaf(acc.x, inv, r.x + b.x);
    o.y = fmaf(acc.y, inv, r.y + b.y);
    if (RELU) { o.x = fmaxf(o.x, 0.f); o.y = fmaxf(o.y, 0.f); }
    float* dstp = TOH ? (g_h + (size_t)w * HID + lane * 2)
                      : (outp + (size_t)w * HID + lane * 2);
    *(float2*)dstp = o;
}

// ---------------- launch ----------------
extern "C" void kernel_launch(void* const* d_in, const int* in_sizes, int n_in,
                              void* d_out, int out_size) {
    const float* x   = (const float*)d_in[0];
    const int*   ei  = (const int*)d_in[1];
    const float* W1l = (const float*)d_in[2];
    const float* b1  = (const float*)d_in[3];
    const float* W1r = (const float*)d_in[4];
    const float* W2l = (const float*)d_in[5];
    const float* b2  = (const float*)d_in[6];
    const float* W2r = (const float*)d_in[7];
    float* out = (float*)d_out;

    const int gGemm = NNODES / 64;                // 625
    const int gPull = (NNODES * 32 + 255) / 256;  // 5000
    const int gE    = (NEDGES + 255) / 256;

    // CSR build
    k_zero_deg<<<(NNODES + 255) / 256, 256>>>();
    k_count<<<gE, 256>>>(ei);
    k_scanA<<<NB_SCAN, 256>>>();
    k_scanB<<<1, 256>>>();
    k_scanC<<<NB_SCAN, 256>>>();
    k_scatter<<<gE, 256>>>(ei);

    // layer 1
    k_gemm_dual<INDIM, false><<<gGemm, 256>>>(x, W1l, W1r);
    k_pull<true, true><<<gPull, 256>>>(b1, nullptr);

    // layer 2
    k_gemm_dual<HID, true><<<gGemm, 256>>>(nullptr, W2l, W2r);
    k_pull<false, false><<<gPull, 256>>>(b2, out);
}